// round 2
// baseline (speedup 1.0000x reference)
#include <cuda_runtime.h>
#include <cuda_bf16.h>
#include <cstdint>
#include <cstddef>

// Fixed problem dims (setup_inputs): B=4, S=2048 -> M=8192, IN=K=4096, OUT=N=4096
#define KDIM 4096
#define NDIM 4096
#define MMAX 8192

#define BM 128
#define BN 128
#define BK 128
#define STAGES 3
#define KT (KDIM / BK)          // 32 k-tiles
#define STAGE_BYTES (BM * BK + BN * BK)   // 32768
#define SMEM_TOTAL (STAGES * STAGE_BYTES) // 98304

// -------- device scratch (no allocs allowed) --------
__device__ int8_t g_A8[(size_t)MMAX * KDIM];   // 32 MB quantized activations
__device__ int8_t g_B8[(size_t)NDIM * KDIM];   // 16 MB int8 weights
__device__ float  g_comb[KDIM];                // input_scale / act_scale
__device__ float  g_sc[NDIM];                  // act_scale * w_scale

// -------- helpers --------
__device__ __forceinline__ uint32_t smem_u32(const void* p) {
    uint32_t a;
    asm("{ .reg .u64 t; cvta.to.shared.u64 t, %1; cvt.u32.u64 %0, t; }" : "=r"(a) : "l"(p));
    return a;
}
__device__ __forceinline__ void cp16(uint32_t s, const void* g) {
    asm volatile("cp.async.cg.shared.global [%0], [%1], 16;" :: "r"(s), "l"(g));
}
__device__ __forceinline__ void ldsm4(uint32_t* d, uint32_t addr) {
    asm volatile("ldmatrix.sync.aligned.m8n8.x4.shared.b16 {%0,%1,%2,%3}, [%4];"
                 : "=r"(d[0]), "=r"(d[1]), "=r"(d[2]), "=r"(d[3]) : "r"(addr));
}
__device__ __forceinline__ void imma(int* c, const uint32_t* a, const uint32_t* b) {
    asm volatile(
        "mma.sync.aligned.m16n8k32.row.col.s32.s8.s8.s32 "
        "{%0,%1,%2,%3}, {%4,%5,%6,%7}, {%8,%9}, {%0,%1,%2,%3};"
        : "+r"(c[0]), "+r"(c[1]), "+r"(c[2]), "+r"(c[3])
        : "r"(a[0]), "r"(a[1]), "r"(a[2]), "r"(a[3]), "r"(b[0]), "r"(b[1]));
}

// -------- preprocessing --------
__global__ void precomp_scales(const float* __restrict__ in_scale,
                               const float* __restrict__ act,
                               const float* __restrict__ w_scale) {
    int i = blockIdx.x * blockDim.x + threadIdx.x;
    float a = act[0];
    if (i < KDIM) g_comb[i] = __fdiv_rn(in_scale[i], a);
    if (i < NDIM) g_sc[i] = a * w_scale[i];
}

__global__ void quant_x(const float* __restrict__ x, int total4) {
    int i = blockIdx.x * blockDim.x + threadIdx.x;
    if (i >= total4) return;
    float4 v = reinterpret_cast<const float4*>(x)[i];
    int col = (i & (KDIM / 4 - 1)) * 4;
    int q0 = min(max(__float2int_rn(v.x * g_comb[col + 0]), -127), 127);
    int q1 = min(max(__float2int_rn(v.y * g_comb[col + 1]), -127), 127);
    int q2 = min(max(__float2int_rn(v.z * g_comb[col + 2]), -127), 127);
    int q3 = min(max(__float2int_rn(v.w * g_comb[col + 3]), -127), 127);
    uint32_t p = (uint32_t)(q0 & 0xFF) | ((uint32_t)(q1 & 0xFF) << 8) |
                 ((uint32_t)(q2 & 0xFF) << 16) | ((uint32_t)(q3 & 0xFF) << 24);
    reinterpret_cast<uint32_t*>(g_A8)[i] = p;
}

__global__ void conv_w(const int* __restrict__ w, int total4) {
    int i = blockIdx.x * blockDim.x + threadIdx.x;
    if (i >= total4) return;
    int4 v = reinterpret_cast<const int4*>(w)[i];
    uint32_t p = (uint32_t)(v.x & 0xFF) | ((uint32_t)(v.y & 0xFF) << 8) |
                 ((uint32_t)(v.z & 0xFF) << 16) | ((uint32_t)(v.w & 0xFF) << 24);
    reinterpret_cast<uint32_t*>(g_B8)[i] = p;
}

// -------- GEMM --------
// smem per stage: A (BM x 128 int8, swizzled) then B (BN x 128)
__device__ __forceinline__ void load_stage(uint32_t sm, const char* gA, const char* gB,
                                           int kt, int tid) {
    const char* ga = gA + (size_t)kt * BK;
    const char* gb = gB + (size_t)kt * BK;
#pragma unroll
    for (int i = 0; i < 4; i++) {
        int slot = tid + i * 256;
        int row = slot >> 3, seg = slot & 7;
        cp16(sm + row * 128 + (((seg ^ (row & 7)) << 4)),
             ga + (size_t)row * KDIM + seg * 16);
    }
#pragma unroll
    for (int i = 0; i < 4; i++) {
        int slot = tid + i * 256;
        int row = slot >> 3, seg = slot & 7;
        cp16(sm + BM * 128 + row * 128 + ((seg ^ (row & 7)) << 4),
             gb + (size_t)row * KDIM + seg * 16);
    }
}

__global__ __launch_bounds__(256, 2)
void gemm_kernel(const float* __restrict__ bias, float* __restrict__ out) {
    extern __shared__ char smem[];
    uint32_t sb = smem_u32(smem);
    int tid = threadIdx.x, lane = tid & 31, wid = tid >> 5;
    int warp_m = wid >> 1, warp_n = wid & 1;   // 4 x 2 warps, warp tile 32 x 64
    int ntile = blockIdx.x, mtile = blockIdx.y;

    const char* gA = (const char*)g_A8 + (size_t)mtile * BM * KDIM;
    const char* gB = (const char*)g_B8 + (size_t)ntile * BN * KDIM;

    // ldmatrix per-lane addressing
    int t = lane >> 3, r = lane & 7;
    int rowA[2], rowB[4];
#pragma unroll
    for (int im = 0; im < 2; im++) rowA[im] = warp_m * 32 + im * 16 + (t & 1) * 8 + r;
    int segA = t >> 1;
#pragma unroll
    for (int nb = 0; nb < 4; nb++) rowB[nb] = warp_n * 64 + nb * 16 + (t >> 1) * 8 + r;
    int segB = t & 1;

    int c[2][8][4];
#pragma unroll
    for (int im = 0; im < 2; im++)
#pragma unroll
        for (int n8 = 0; n8 < 8; n8++)
#pragma unroll
            for (int q = 0; q < 4; q++) c[im][n8][q] = 0;

    // prologue: stages 0, 1
    load_stage(sb + 0 * STAGE_BYTES, gA, gB, 0, tid);
    asm volatile("cp.async.commit_group;" ::: "memory");
    load_stage(sb + 1 * STAGE_BYTES, gA, gB, 1, tid);
    asm volatile("cp.async.commit_group;" ::: "memory");

#pragma unroll 1
    for (int kt = 0; kt < KT; kt++) {
        int s = kt % STAGES;
        asm volatile("cp.async.wait_group 1;" ::: "memory");
        __syncthreads();

        if (kt + 2 < KT) load_stage(sb + ((kt + 2) % STAGES) * STAGE_BYTES, gA, gB, kt + 2, tid);
        asm volatile("cp.async.commit_group;" ::: "memory");

        uint32_t sA = sb + s * STAGE_BYTES;
        uint32_t sB = sA + BM * 128;

#pragma unroll
        for (int j = 0; j < 4; j++) {   // four k32 steps within BK=128
            uint32_t a[2][4];
#pragma unroll
            for (int im = 0; im < 2; im++) {
                int seg = 2 * j + segA;
                ldsm4(a[im], sA + rowA[im] * 128 + ((seg ^ (rowA[im] & 7)) << 4));
            }
            uint32_t bfr[8][2];
#pragma unroll
            for (int nb = 0; nb < 4; nb++) {
                uint32_t r4[4];
                int seg = 2 * j + segB;
                ldsm4(r4, sB + rowB[nb] * 128 + ((seg ^ (rowB[nb] & 7)) << 4));
                bfr[2 * nb][0] = r4[0]; bfr[2 * nb][1] = r4[1];
                bfr[2 * nb + 1][0] = r4[2]; bfr[2 * nb + 1][1] = r4[3];
            }
#pragma unroll
            for (int im = 0; im < 2; im++)
#pragma unroll
                for (int n8 = 0; n8 < 8; n8++)
                    imma(c[im][n8], a[im], bfr[n8]);
        }
    }

    // epilogue: dequant + bias, direct stores
    int m0 = mtile * BM + warp_m * 32 + (lane >> 2);
    int n0 = ntile * BN + warp_n * 64 + (lane & 3) * 2;
#pragma unroll
    for (int im = 0; im < 2; im++) {
#pragma unroll
        for (int n8 = 0; n8 < 8; n8++) {
            int col = n0 + n8 * 8;
            float2 sc = *reinterpret_cast<const float2*>(&g_sc[col]);
            float2 bi = *reinterpret_cast<const float2*>(&bias[col]);
            int r0 = m0 + im * 16, r1 = r0 + 8;
            float2 v0, v1;
            v0.x = (float)c[im][n8][0] * sc.x + bi.x;
            v0.y = (float)c[im][n8][1] * sc.y + bi.y;
            v1.x = (float)c[im][n8][2] * sc.x + bi.x;
            v1.y = (float)c[im][n8][3] * sc.y + bi.y;
            *reinterpret_cast<float2*>(out + (size_t)r0 * NDIM + col) = v0;
            *reinterpret_cast<float2*>(out + (size_t)r1 * NDIM + col) = v1;
        }
    }
}

// -------- launch --------
extern "C" void kernel_launch(void* const* d_in, const int* in_sizes, int n_in,
                              void* d_out, int out_size) {
    const float* x        = (const float*)d_in[0];
    const float* in_scale = (const float*)d_in[1];
    const float* act      = (const float*)d_in[2];
    const int*   w        = (const int*)d_in[3];
    const float* w_scale  = (const float*)d_in[4];
    const float* bias     = (const float*)d_in[5];
    float* out = (float*)d_out;

    int M = in_sizes[0] / KDIM;  // 8192

    cudaFuncSetAttribute(gemm_kernel, cudaFuncAttributeMaxDynamicSharedMemorySize, SMEM_TOTAL);

    precomp_scales<<<(KDIM + 255) / 256, 256>>>(in_scale, act, w_scale);

    int xa4 = (M * KDIM) / 4;
    quant_x<<<(xa4 + 255) / 256, 256>>>(x, xa4);

    int wb4 = (NDIM * KDIM) / 4;
    conv_w<<<(wb4 + 255) / 256, 256>>>(w, wb4);

    dim3 grid(NDIM / BN, M / BM);
    gemm_kernel<<<grid, 256, SMEM_TOTAL>>>(bias, out);
}

// round 3
// speedup vs baseline: 1.3595x; 1.3595x over previous
#include <cuda_runtime.h>
#include <cuda_bf16.h>
#include <cstdint>
#include <cstddef>

// Fixed problem dims: B=4, S=2048 -> M=8192, K=4096, N=4096
#define KDIM 4096
#define NDIM 4096
#define MMAX 8192

#define BM 128
#define BN 128
#define BK 128
#define KT (KDIM / BK)      // 32 k-tiles
#define KI 20               // k-tiles done by IMMA warps (0..KI)
#define KD (KT - KI)        // k-tiles done by dp4a warps

#define STAGE_BYTES (BM * BK + BN * BK)       // 32768 (A 16K + B 16K)
#define IMMA_STAGES 3
#define DP_OFF (IMMA_STAGES * STAGE_BYTES)    // 98304
#define PART_STRIDE 132                        // padded int32 row stride
#define SMEM_TOTAL (DP_OFF + BM * PART_STRIDE * 4)  // 98304 + 67584 = 165888

// -------- device scratch --------
__device__ int8_t g_A8[(size_t)MMAX * KDIM];
__device__ int8_t g_B8[(size_t)NDIM * KDIM];
__device__ float  g_comb[KDIM];
__device__ float  g_sc[NDIM];

// -------- helpers --------
__device__ __forceinline__ uint32_t smem_u32(const void* p) {
    uint32_t a;
    asm("{ .reg .u64 t; cvta.to.shared.u64 t, %1; cvt.u32.u64 %0, t; }" : "=r"(a) : "l"(p));
    return a;
}
__device__ __forceinline__ void cp16(uint32_t s, const void* g) {
    asm volatile("cp.async.cg.shared.global [%0], [%1], 16;" :: "r"(s), "l"(g));
}
__device__ __forceinline__ void ldsm4(uint32_t* d, uint32_t addr) {
    asm volatile("ldmatrix.sync.aligned.m8n8.x4.shared.b16 {%0,%1,%2,%3}, [%4];"
                 : "=r"(d[0]), "=r"(d[1]), "=r"(d[2]), "=r"(d[3]) : "r"(addr));
}
__device__ __forceinline__ void imma(int* c, const uint32_t* a, const uint32_t* b) {
    asm volatile(
        "mma.sync.aligned.m16n8k32.row.col.s32.s8.s8.s32 "
        "{%0,%1,%2,%3}, {%4,%5,%6,%7}, {%8,%9}, {%0,%1,%2,%3};"
        : "+r"(c[0]), "+r"(c[1]), "+r"(c[2]), "+r"(c[3])
        : "r"(a[0]), "r"(a[1]), "r"(a[2]), "r"(a[3]), "r"(b[0]), "r"(b[1]));
}
__device__ __forceinline__ void dp4a_acc(int& c, uint32_t a, uint32_t b) {
    asm volatile("dp4a.s32.s32 %0, %1, %2, %0;" : "+r"(c) : "r"(a), "r"(b));
}

// -------- preprocessing --------
__global__ void precomp_scales(const float* __restrict__ in_scale,
                               const float* __restrict__ act,
                               const float* __restrict__ w_scale) {
    int i = blockIdx.x * blockDim.x + threadIdx.x;
    float a = act[0];
    if (i < KDIM) g_comb[i] = __fdiv_rn(in_scale[i], a);
    if (i < NDIM) g_sc[i] = a * w_scale[i];
}

__global__ void quant_x(const float* __restrict__ x, int total4) {
    int i = blockIdx.x * blockDim.x + threadIdx.x;
    if (i >= total4) return;
    float4 v = reinterpret_cast<const float4*>(x)[i];
    int col = (i & (KDIM / 4 - 1)) * 4;
    int q0 = min(max(__float2int_rn(v.x * g_comb[col + 0]), -127), 127);
    int q1 = min(max(__float2int_rn(v.y * g_comb[col + 1]), -127), 127);
    int q2 = min(max(__float2int_rn(v.z * g_comb[col + 2]), -127), 127);
    int q3 = min(max(__float2int_rn(v.w * g_comb[col + 3]), -127), 127);
    uint32_t p = (uint32_t)(q0 & 0xFF) | ((uint32_t)(q1 & 0xFF) << 8) |
                 ((uint32_t)(q2 & 0xFF) << 16) | ((uint32_t)(q3 & 0xFF) << 24);
    reinterpret_cast<uint32_t*>(g_A8)[i] = p;
}

__global__ void conv_w(const int* __restrict__ w, int total4) {
    int i = blockIdx.x * blockDim.x + threadIdx.x;
    if (i >= total4) return;
    int4 v = reinterpret_cast<const int4*>(w)[i];
    uint32_t p = (uint32_t)(v.x & 0xFF) | ((uint32_t)(v.y & 0xFF) << 8) |
                 ((uint32_t)(v.z & 0xFF) << 16) | ((uint32_t)(v.w & 0xFF) << 24);
    reinterpret_cast<uint32_t*>(g_B8)[i] = p;
}

// -------- shared tile loader (A then B, XOR-swizzled, 256 threads) --------
__device__ __forceinline__ void load_stage(uint32_t sm, const char* gA, const char* gB,
                                           int kt, int t) {
    const char* ga = gA + (size_t)kt * BK;
    const char* gb = gB + (size_t)kt * BK;
#pragma unroll
    for (int i = 0; i < 4; i++) {
        int slot = t + i * 256;
        int row = slot >> 3, seg = slot & 7;
        cp16(sm + row * 128 + ((seg ^ (row & 7)) << 4),
             ga + (size_t)row * KDIM + seg * 16);
    }
#pragma unroll
    for (int i = 0; i < 4; i++) {
        int slot = t + i * 256;
        int row = slot >> 3, seg = slot & 7;
        cp16(sm + BM * 128 + row * 128 + ((seg ^ (row & 7)) << 4),
             gb + (size_t)row * KDIM + seg * 16);
    }
}

// -------- hybrid GEMM kernel: 512 threads, warps 0-7 IMMA, warps 8-15 dp4a --------
__global__ __launch_bounds__(512, 1)
void gemm_kernel(const float* __restrict__ bias, float* __restrict__ out) {
    extern __shared__ __align__(1024) char smem[];
    uint32_t sb = smem_u32(smem);
    int tid = threadIdx.x;
    int ntile = blockIdx.x, mtile = blockIdx.y;

    const char* gA = (const char*)g_A8 + (size_t)mtile * BM * KDIM;
    const char* gB = (const char*)g_B8 + (size_t)ntile * BN * KDIM;

    int c[2][8][4];    // IMMA accumulators (tid < 256)

    if (tid < 256) {
        // ================= IMMA group: k-tiles [0, KI) =================
        int lane = tid & 31, wid = tid >> 5;
        int warp_m = wid >> 1, warp_n = wid & 1;     // 4x2 warps, warp tile 32x64

        int t = lane >> 3, r = lane & 7;
        int rowA[2], rowB[4];
#pragma unroll
        for (int im = 0; im < 2; im++) rowA[im] = warp_m * 32 + im * 16 + (t & 1) * 8 + r;
        int segA = t >> 1;
#pragma unroll
        for (int nb = 0; nb < 4; nb++) rowB[nb] = warp_n * 64 + nb * 16 + (t >> 1) * 8 + r;
        int segB = t & 1;

#pragma unroll
        for (int im = 0; im < 2; im++)
#pragma unroll
            for (int n8 = 0; n8 < 8; n8++)
#pragma unroll
                for (int q = 0; q < 4; q++) c[im][n8][q] = 0;

        load_stage(sb + 0 * STAGE_BYTES, gA, gB, 0, tid);
        asm volatile("cp.async.commit_group;" ::: "memory");
        load_stage(sb + 1 * STAGE_BYTES, gA, gB, 1, tid);
        asm volatile("cp.async.commit_group;" ::: "memory");

#pragma unroll 1
        for (int kt = 0; kt < KI; kt++) {
            int s = kt % IMMA_STAGES;
            asm volatile("cp.async.wait_group 1;" ::: "memory");
            asm volatile("bar.sync 1, 256;" ::: "memory");

            if (kt + 2 < KI)
                load_stage(sb + ((kt + 2) % IMMA_STAGES) * STAGE_BYTES, gA, gB, kt + 2, tid);
            asm volatile("cp.async.commit_group;" ::: "memory");

            uint32_t sA = sb + s * STAGE_BYTES;
            uint32_t sB = sA + BM * 128;

#pragma unroll
            for (int j = 0; j < 4; j++) {
                uint32_t a[2][4];
#pragma unroll
                for (int im = 0; im < 2; im++) {
                    int seg = 2 * j + segA;
                    ldsm4(a[im], sA + rowA[im] * 128 + ((seg ^ (rowA[im] & 7)) << 4));
                }
                uint32_t bfr[8][2];
#pragma unroll
                for (int nb = 0; nb < 4; nb++) {
                    uint32_t r4[4];
                    int seg = 2 * j + segB;
                    ldsm4(r4, sB + rowB[nb] * 128 + ((seg ^ (rowB[nb] & 7)) << 4));
                    bfr[2 * nb][0] = r4[0]; bfr[2 * nb][1] = r4[1];
                    bfr[2 * nb + 1][0] = r4[2]; bfr[2 * nb + 1][1] = r4[3];
                }
#pragma unroll
                for (int im = 0; im < 2; im++)
#pragma unroll
                    for (int n8 = 0; n8 < 8; n8++)
                        imma(c[im][n8], a[im], bfr[n8]);
            }
        }
    } else {
        // ================= dp4a group: k-tiles [KI, KT) =================
        int dt = tid - 256;
        int dl = dt & 31, dwid = dt >> 5;
        int wm = dwid >> 2, wn = dwid & 3;   // 2x4 warps, warp tile 64x32
        int tm = dl >> 2, tn = dl & 3;       // 8x4 threads, thread tile 8x8

        int cd[8][8];
#pragma unroll
        for (int i = 0; i < 8; i++)
#pragma unroll
            for (int j = 0; j < 8; j++) cd[i][j] = 0;

        uint32_t dbuf0 = sb + DP_OFF;
        uint32_t dbuf1 = sb + DP_OFF + STAGE_BYTES;

        load_stage(dbuf0, gA, gB, KI, dt);
        asm volatile("cp.async.commit_group;" ::: "memory");

#pragma unroll 1
        for (int kt = 0; kt < KD; kt++) {
            if (kt + 1 < KD) {
                load_stage((kt & 1) ? dbuf0 : dbuf1, gA, gB, KI + kt + 1, dt);
                asm volatile("cp.async.commit_group;" ::: "memory");
                asm volatile("cp.async.wait_group 1;" ::: "memory");
            } else {
                asm volatile("cp.async.wait_group 0;" ::: "memory");
            }
            asm volatile("bar.sync 2, 256;" ::: "memory");

            uint32_t sA = (kt & 1) ? dbuf1 : dbuf0;
            uint32_t sB = sA + BM * 128;

            // per-thread base addresses (low bits 4-6 hold the XOR-swizzle key)
            uint32_t aA = sA + (uint32_t)((wm * 64 + tm) * 128 + (tm << 4));
            uint32_t bE = sB + (uint32_t)((wn * 32 + tn) * 128 + (tn << 4));
            uint32_t bO = bE + 512 + 64;

#pragma unroll 1
            for (int seg = 0; seg < 8; seg++) {
                uint32_t as  = aA ^ (uint32_t)(seg << 4);
                uint32_t bsE = bE ^ (uint32_t)(seg << 4);
                uint32_t bsO = bO ^ (uint32_t)(seg << 4);
#pragma unroll
                for (int h = 0; h < 2; h++) {
                    uint32_t a[8][2], b[8][2];
#pragma unroll
                    for (int i = 0; i < 8; i++)
                        asm volatile("ld.shared.v2.b32 {%0,%1}, [%2];"
                                     : "=r"(a[i][0]), "=r"(a[i][1])
                                     : "r"(as + i * 1024 + h * 8));
#pragma unroll
                    for (int j = 0; j < 8; j++) {
                        uint32_t base = (j & 1) ? bsO : bsE;
                        asm volatile("ld.shared.v2.b32 {%0,%1}, [%2];"
                                     : "=r"(b[j][0]), "=r"(b[j][1])
                                     : "r"(base + (j >> 1) * 1024 + h * 8));
                    }
#pragma unroll
                    for (int i = 0; i < 8; i++)
#pragma unroll
                        for (int j = 0; j < 8; j++) {
                            dp4a_acc(cd[i][j], a[i][0], b[j][0]);
                            dp4a_acc(cd[i][j], a[i][1], b[j][1]);
                        }
                }
            }
            asm volatile("bar.sync 2, 256;" ::: "memory");
        }

        // write partial int32 sums to smem (conflict-free via stride 132)
        int* part = (int*)(smem + DP_OFF);
        int prow = wm * 64 + tm, pcol = wn * 32 + tn;
#pragma unroll
        for (int i = 0; i < 8; i++)
#pragma unroll
            for (int j = 0; j < 8; j++)
                part[(prow + 8 * i) * PART_STRIDE + pcol + 4 * j] = cd[i][j];
    }

    __syncthreads();   // dp4a partials visible; IMMA warps done

    if (tid < 256) {
        // ============ merged epilogue: add partials, dequant, store ============
        int lane = tid & 31, wid = tid >> 5;
        int warp_m = wid >> 1, warp_n = wid & 1;
        const int* part = (const int*)(smem + DP_OFF);

        int rl = warp_m * 32 + (lane >> 2);
        int cl = warp_n * 64 + (lane & 3) * 2;
        int m0 = mtile * BM + rl;
        int n0 = ntile * BN + cl;

#pragma unroll
        for (int im = 0; im < 2; im++) {
#pragma unroll
            for (int n8 = 0; n8 < 8; n8++) {
                int col = n0 + n8 * 8;
                int lc = cl + n8 * 8;
                float2 sc = *reinterpret_cast<const float2*>(&g_sc[col]);
                float2 bi = *reinterpret_cast<const float2*>(&bias[col]);
                int r0l = rl + im * 16, r1l = r0l + 8;
                int p00 = part[r0l * PART_STRIDE + lc];
                int p01 = part[r0l * PART_STRIDE + lc + 1];
                int p10 = part[r1l * PART_STRIDE + lc];
                int p11 = part[r1l * PART_STRIDE + lc + 1];
                int r0 = m0 + im * 16, r1 = r0 + 8;
                float2 v0, v1;
                v0.x = (float)(c[im][n8][0] + p00) * sc.x + bi.x;
                v0.y = (float)(c[im][n8][1] + p01) * sc.y + bi.y;
                v1.x = (float)(c[im][n8][2] + p10) * sc.x + bi.x;
                v1.y = (float)(c[im][n8][3] + p11) * sc.y + bi.y;
                *reinterpret_cast<float2*>(out + (size_t)r0 * NDIM + col) = v0;
                *reinterpret_cast<float2*>(out + (size_t)r1 * NDIM + col) = v1;
            }
        }
    }
}

// -------- launch --------
extern "C" void kernel_launch(void* const* d_in, const int* in_sizes, int n_in,
                              void* d_out, int out_size) {
    const float* x        = (const float*)d_in[0];
    const float* in_scale = (const float*)d_in[1];
    const float* act      = (const float*)d_in[2];
    const int*   w        = (const int*)d_in[3];
    const float* w_scale  = (const float*)d_in[4];
    const float* bias     = (const float*)d_in[5];
    float* out = (float*)d_out;

    int M = in_sizes[0] / KDIM;  // 8192

    cudaFuncSetAttribute(gemm_kernel, cudaFuncAttributeMaxDynamicSharedMemorySize, SMEM_TOTAL);

    precomp_scales<<<(KDIM + 255) / 256, 256>>>(in_scale, act, w_scale);

    int xa4 = (M * KDIM) / 4;
    quant_x<<<(xa4 + 255) / 256, 256>>>(x, xa4);

    int wb4 = (NDIM * KDIM) / 4;
    conv_w<<<(wb4 + 255) / 256, 256>>>(w, wb4);

    dim3 grid(NDIM / BN, M / BM);
    gemm_kernel<<<grid, 512, SMEM_TOTAL>>>(bias, out);
}

// round 4
// speedup vs baseline: 1.3955x; 1.0264x over previous
#include <cuda_runtime.h>
#include <cuda_bf16.h>
#include <cstdint>
#include <cstddef>

// Fixed problem dims: B=4, S=2048 -> M=8192, K=4096, N=4096
#define KDIM 4096
#define NDIM 4096
#define MMAX 8192

#define BM 128
#define BN 128
#define BK 128
#define KT (KDIM / BK)      // 32 k-tiles
#define KI 16               // k-tiles done by IMMA warps [0, KI)
#define KD (KT - KI)        // k-tiles done by dp4a warps [KI, KT)

#define STAGE_BYTES (BM * BK + BN * BK)       // 32768 (A 16K + B 16K)
#define IMMA_STAGES 3
#define DP_OFF (IMMA_STAGES * STAGE_BYTES)    // 98304
#define PART_STRIDE 132                        // padded int32 row stride
#define SMEM_TOTAL (DP_OFF + BM * PART_STRIDE * 4)  // 98304 + 67584 = 165888

// -------- device scratch --------
__device__ int8_t g_A8[(size_t)MMAX * KDIM];
__device__ int8_t g_B8[(size_t)NDIM * KDIM];
__device__ float  g_comb[KDIM];
__device__ float  g_sc[NDIM];

// -------- helpers --------
__device__ __forceinline__ uint32_t smem_u32(const void* p) {
    uint32_t a;
    asm("{ .reg .u64 t; cvta.to.shared.u64 t, %1; cvt.u32.u64 %0, t; }" : "=r"(a) : "l"(p));
    return a;
}
__device__ __forceinline__ void cp16(uint32_t s, const void* g) {
    asm volatile("cp.async.cg.shared.global [%0], [%1], 16;" :: "r"(s), "l"(g));
}
__device__ __forceinline__ void ldsm4(uint32_t* d, uint32_t addr) {
    asm volatile("ldmatrix.sync.aligned.m8n8.x4.shared.b16 {%0,%1,%2,%3}, [%4];"
                 : "=r"(d[0]), "=r"(d[1]), "=r"(d[2]), "=r"(d[3]) : "r"(addr));
}
__device__ __forceinline__ void imma(int* c, const uint32_t* a, const uint32_t* b) {
    asm volatile(
        "mma.sync.aligned.m16n8k32.row.col.s32.s8.s8.s32 "
        "{%0,%1,%2,%3}, {%4,%5,%6,%7}, {%8,%9}, {%0,%1,%2,%3};"
        : "+r"(c[0]), "+r"(c[1]), "+r"(c[2]), "+r"(c[3])
        : "r"(a[0]), "r"(a[1]), "r"(a[2]), "r"(a[3]), "r"(b[0]), "r"(b[1]));
}
__device__ __forceinline__ void dp4a_acc(int& c, uint32_t a, uint32_t b) {
    asm volatile("dp4a.s32.s32 %0, %1, %2, %0;" : "+r"(c) : "r"(a), "r"(b));
}

// -------- preprocessing --------
__global__ void precomp_scales(const float* __restrict__ in_scale,
                               const float* __restrict__ act,
                               const float* __restrict__ w_scale) {
    int i = blockIdx.x * blockDim.x + threadIdx.x;
    float a = act[0];
    if (i < KDIM) g_comb[i] = __fdiv_rn(in_scale[i], a);
    if (i < NDIM) g_sc[i] = a * w_scale[i];
}

__global__ void quant_x(const float* __restrict__ x, int total4) {
    int i = blockIdx.x * blockDim.x + threadIdx.x;
    if (i >= total4) return;
    float4 v = reinterpret_cast<const float4*>(x)[i];
    int col = (i & (KDIM / 4 - 1)) * 4;
    int q0 = min(max(__float2int_rn(v.x * g_comb[col + 0]), -127), 127);
    int q1 = min(max(__float2int_rn(v.y * g_comb[col + 1]), -127), 127);
    int q2 = min(max(__float2int_rn(v.z * g_comb[col + 2]), -127), 127);
    int q3 = min(max(__float2int_rn(v.w * g_comb[col + 3]), -127), 127);
    uint32_t p = (uint32_t)(q0 & 0xFF) | ((uint32_t)(q1 & 0xFF) << 8) |
                 ((uint32_t)(q2 & 0xFF) << 16) | ((uint32_t)(q3 & 0xFF) << 24);
    reinterpret_cast<uint32_t*>(g_A8)[i] = p;
}

__global__ void conv_w(const int* __restrict__ w, int total4) {
    int i = blockIdx.x * blockDim.x + threadIdx.x;
    if (i >= total4) return;
    int4 v = reinterpret_cast<const int4*>(w)[i];
    uint32_t p = (uint32_t)(v.x & 0xFF) | ((uint32_t)(v.y & 0xFF) << 8) |
                 ((uint32_t)(v.z & 0xFF) << 16) | ((uint32_t)(v.w & 0xFF) << 24);
    reinterpret_cast<uint32_t*>(g_B8)[i] = p;
}

// -------- shared tile loader (A then B, XOR-swizzled, 256 threads) --------
__device__ __forceinline__ void load_stage(uint32_t sm, const char* gA, const char* gB,
                                           int kt, int t) {
    const char* ga = gA + (size_t)kt * BK;
    const char* gb = gB + (size_t)kt * BK;
#pragma unroll
    for (int i = 0; i < 4; i++) {
        int slot = t + i * 256;
        int row = slot >> 3, seg = slot & 7;
        cp16(sm + row * 128 + ((seg ^ (row & 7)) << 4),
             ga + (size_t)row * KDIM + seg * 16);
    }
#pragma unroll
    for (int i = 0; i < 4; i++) {
        int slot = t + i * 256;
        int row = slot >> 3, seg = slot & 7;
        cp16(sm + BM * 128 + row * 128 + ((seg ^ (row & 7)) << 4),
             gb + (size_t)row * KDIM + seg * 16);
    }
}

// -------- hybrid GEMM kernel: 512 threads, warps 0-7 IMMA, warps 8-15 dp4a --------
__global__ __launch_bounds__(512, 1)
void gemm_kernel(const float* __restrict__ bias, float* __restrict__ out) {
    extern __shared__ __align__(1024) char smem[];
    uint32_t sb = smem_u32(smem);
    int tid = threadIdx.x;
    int ntile = blockIdx.x, mtile = blockIdx.y;

    const char* gA = (const char*)g_A8 + (size_t)mtile * BM * KDIM;
    const char* gB = (const char*)g_B8 + (size_t)ntile * BN * KDIM;

    int c[2][8][4];    // IMMA accumulators (tid < 256)

    if (tid < 256) {
        // ================= IMMA group: k-tiles [0, KI) =================
        int lane = tid & 31, wid = tid >> 5;
        int warp_m = wid >> 1, warp_n = wid & 1;     // 4x2 warps, warp tile 32x64

        int t = lane >> 3, r = lane & 7;
        int rowA[2], rowB[4];
#pragma unroll
        for (int im = 0; im < 2; im++) rowA[im] = warp_m * 32 + im * 16 + (t & 1) * 8 + r;
        int segA = t >> 1;
#pragma unroll
        for (int nb = 0; nb < 4; nb++) rowB[nb] = warp_n * 64 + nb * 16 + (t >> 1) * 8 + r;
        int segB = t & 1;

#pragma unroll
        for (int im = 0; im < 2; im++)
#pragma unroll
            for (int n8 = 0; n8 < 8; n8++)
#pragma unroll
                for (int q = 0; q < 4; q++) c[im][n8][q] = 0;

        load_stage(sb + 0 * STAGE_BYTES, gA, gB, 0, tid);
        asm volatile("cp.async.commit_group;" ::: "memory");
        load_stage(sb + 1 * STAGE_BYTES, gA, gB, 1, tid);
        asm volatile("cp.async.commit_group;" ::: "memory");

#pragma unroll 1
        for (int kt = 0; kt < KI; kt++) {
            int s = kt % IMMA_STAGES;
            asm volatile("cp.async.wait_group 1;" ::: "memory");
            asm volatile("bar.sync 1, 256;" ::: "memory");

            if (kt + 2 < KI)
                load_stage(sb + ((kt + 2) % IMMA_STAGES) * STAGE_BYTES, gA, gB, kt + 2, tid);
            asm volatile("cp.async.commit_group;" ::: "memory");

            uint32_t sA = sb + s * STAGE_BYTES;
            uint32_t sB = sA + BM * 128;

#pragma unroll
            for (int j = 0; j < 4; j++) {
                uint32_t a[2][4];
#pragma unroll
                for (int im = 0; im < 2; im++) {
                    int seg = 2 * j + segA;
                    ldsm4(a[im], sA + rowA[im] * 128 + ((seg ^ (rowA[im] & 7)) << 4));
                }
                uint32_t bfr[8][2];
#pragma unroll
                for (int nb = 0; nb < 4; nb++) {
                    uint32_t r4[4];
                    int seg = 2 * j + segB;
                    ldsm4(r4, sB + rowB[nb] * 128 + ((seg ^ (rowB[nb] & 7)) << 4));
                    bfr[2 * nb][0] = r4[0]; bfr[2 * nb][1] = r4[1];
                    bfr[2 * nb + 1][0] = r4[2]; bfr[2 * nb + 1][1] = r4[3];
                }
#pragma unroll
                for (int im = 0; im < 2; im++)
#pragma unroll
                    for (int n8 = 0; n8 < 8; n8++)
                        imma(c[im][n8], a[im], bfr[n8]);
            }
        }
    } else {
        // ================= dp4a group: k-tiles [KI, KT) =================
        int dt = tid - 256;
        int dl = dt & 31, dwid = dt >> 5;
        int wm = dwid >> 2, wn = dwid & 3;   // 2x4 warps, warp tile 64x32
        int tm = dl >> 2, tn = dl & 3;       // 8x4 threads, thread tile 8x8

        int cd[8][8];
#pragma unroll
        for (int i = 0; i < 8; i++)
#pragma unroll
            for (int j = 0; j < 8; j++) cd[i][j] = 0;

        uint32_t dbuf0 = sb + DP_OFF;
        uint32_t dbuf1 = sb + DP_OFF + STAGE_BYTES;

        load_stage(dbuf0, gA, gB, KI, dt);
        asm volatile("cp.async.commit_group;" ::: "memory");

#pragma unroll 1
        for (int kt = 0; kt < KD; kt++) {
            if (kt + 1 < KD) {
                load_stage((kt & 1) ? dbuf0 : dbuf1, gA, gB, KI + kt + 1, dt);
                asm volatile("cp.async.commit_group;" ::: "memory");
                asm volatile("cp.async.wait_group 1;" ::: "memory");
            } else {
                asm volatile("cp.async.wait_group 0;" ::: "memory");
            }
            asm volatile("bar.sync 2, 256;" ::: "memory");

            uint32_t sA = (kt & 1) ? dbuf1 : dbuf0;
            uint32_t sB = sA + BM * 128;

            // per-thread base addresses (low bits 4-6 hold the XOR-swizzle key)
            uint32_t aA = sA + (uint32_t)((wm * 64 + tm) * 128 + (tm << 4));
            uint32_t bE = sB + (uint32_t)((wn * 32 + tn) * 128 + (tn << 4));
            uint32_t bO = bE + 512 + 64;

#pragma unroll 1
            for (int seg = 0; seg < 8; seg++) {
                uint32_t as  = aA ^ (uint32_t)(seg << 4);
                uint32_t bsE = bE ^ (uint32_t)(seg << 4);
                uint32_t bsO = bO ^ (uint32_t)(seg << 4);
#pragma unroll
                for (int h = 0; h < 2; h++) {
                    uint32_t a[8][2], b[8][2];
#pragma unroll
                    for (int i = 0; i < 8; i++)
                        asm volatile("ld.shared.v2.b32 {%0,%1}, [%2];"
                                     : "=r"(a[i][0]), "=r"(a[i][1])
                                     : "r"(as + i * 1024 + h * 8));
#pragma unroll
                    for (int j = 0; j < 8; j++) {
                        uint32_t base = (j & 1) ? bsO : bsE;
                        asm volatile("ld.shared.v2.b32 {%0,%1}, [%2];"
                                     : "=r"(b[j][0]), "=r"(b[j][1])
                                     : "r"(base + (j >> 1) * 1024 + h * 8));
                    }
#pragma unroll
                    for (int i = 0; i < 8; i++)
#pragma unroll
                        for (int j = 0; j < 8; j++) {
                            dp4a_acc(cd[i][j], a[i][0], b[j][0]);
                            dp4a_acc(cd[i][j], a[i][1], b[j][1]);
                        }
                }
            }
            asm volatile("bar.sync 2, 256;" ::: "memory");
        }

        // write partial int32 sums to smem (conflict-free via stride 132)
        int* part = (int*)(smem + DP_OFF);
        int prow = wm * 64 + tm, pcol = wn * 32 + tn;
#pragma unroll
        for (int i = 0; i < 8; i++)
#pragma unroll
            for (int j = 0; j < 8; j++)
                part[(prow + 8 * i) * PART_STRIDE + pcol + 4 * j] = cd[i][j];
    }

    __syncthreads();   // dp4a partials visible; IMMA warps done

    if (tid < 256) {
        // ============ merged epilogue: add partials, dequant, store ============
        int lane = tid & 31, wid = tid >> 5;
        int warp_m = wid >> 1, warp_n = wid & 1;
        const int* part = (const int*)(smem + DP_OFF);

        int rl = warp_m * 32 + (lane >> 2);
        int cl = warp_n * 64 + (lane & 3) * 2;
        int m0 = mtile * BM + rl;
        int n0 = ntile * BN + cl;

#pragma unroll
        for (int im = 0; im < 2; im++) {
#pragma unroll
            for (int n8 = 0; n8 < 8; n8++) {
                int col = n0 + n8 * 8;
                int lc = cl + n8 * 8;
                float2 sc = *reinterpret_cast<const float2*>(&g_sc[col]);
                float2 bi = *reinterpret_cast<const float2*>(&bias[col]);
                int r0l = rl + im * 16, r1l = r0l + 8;
                int p00 = part[r0l * PART_STRIDE + lc];
                int p01 = part[r0l * PART_STRIDE + lc + 1];
                int p10 = part[r1l * PART_STRIDE + lc];
                int p11 = part[r1l * PART_STRIDE + lc + 1];
                int r0 = m0 + im * 16, r1 = r0 + 8;
                float2 v0, v1;
                v0.x = (float)(c[im][n8][0] + p00) * sc.x + bi.x;
                v0.y = (float)(c[im][n8][1] + p01) * sc.y + bi.y;
                v1.x = (float)(c[im][n8][2] + p10) * sc.x + bi.x;
                v1.y = (float)(c[im][n8][3] + p11) * sc.y + bi.y;
                *reinterpret_cast<float2*>(out + (size_t)r0 * NDIM + col) = v0;
                *reinterpret_cast<float2*>(out + (size_t)r1 * NDIM + col) = v1;
            }
        }
    }
}

// -------- launch --------
extern "C" void kernel_launch(void* const* d_in, const int* in_sizes, int n_in,
                              void* d_out, int out_size) {
    const float* x        = (const float*)d_in[0];
    const float* in_scale = (const float*)d_in[1];
    const float* act      = (const float*)d_in[2];
    const int*   w        = (const int*)d_in[3];
    const float* w_scale  = (const float*)d_in[4];
    const float* bias     = (const float*)d_in[5];
    float* out = (float*)d_out;

    int M = in_sizes[0] / KDIM;  // 8192

    cudaFuncSetAttribute(gemm_kernel, cudaFuncAttributeMaxDynamicSharedMemorySize, SMEM_TOTAL);

    precomp_scales<<<(KDIM + 255) / 256, 256>>>(in_scale, act, w_scale);

    int xa4 = (M * KDIM) / 4;
    quant_x<<<(xa4 + 255) / 256, 256>>>(x, xa4);

    int wb4 = (NDIM * KDIM) / 4;
    conv_w<<<(wb4 + 255) / 256, 256>>>(w, wb4);

    dim3 grid(NDIM / BN, M / BM);
    gemm_kernel<<<grid, 512, SMEM_TOTAL>>>(bias, out);
}

// round 5
// speedup vs baseline: 1.4548x; 1.0425x over previous
#include <cuda_runtime.h>
#include <cuda_bf16.h>
#include <cstdint>
#include <cstddef>

// Fixed problem dims: B=4, S=2048 -> M=8192, K=4096, N=4096
#define KDIM 4096
#define NDIM 4096
#define MMAX 8192

#define BM 128
#define BN 128
#define BK 128
#define KT (KDIM / BK)      // 32 k-tiles
#define KI 18               // k-tiles done by IMMA warps [0, KI)
#define KD (KT - KI)        // k-tiles done by dp4a warps [KI, KT)

#define STAGE_BYTES (BM * BK + BN * BK)       // 32768 (A 16K + B 16K)
#define IMMA_STAGES 3
#define DP_STAGES 3
#define DP_OFF (IMMA_STAGES * STAGE_BYTES)    // 98304
#define PART_STRIDE 132                        // padded int32 row stride
#define SMEM_TOTAL (DP_OFF + DP_STAGES * STAGE_BYTES)  // 196608

// -------- device scratch --------
__device__ int8_t g_A8[(size_t)MMAX * KDIM];
__device__ int8_t g_B8[(size_t)NDIM * KDIM];
__device__ float  g_comb[KDIM];
__device__ float  g_sc[NDIM];

// -------- helpers --------
__device__ __forceinline__ uint32_t smem_u32(const void* p) {
    uint32_t a;
    asm("{ .reg .u64 t; cvta.to.shared.u64 t, %1; cvt.u32.u64 %0, t; }" : "=r"(a) : "l"(p));
    return a;
}
__device__ __forceinline__ void cp16(uint32_t s, const void* g) {
    asm volatile("cp.async.cg.shared.global [%0], [%1], 16;" :: "r"(s), "l"(g));
}
__device__ __forceinline__ void ldsm4(uint32_t* d, uint32_t addr) {
    asm volatile("ldmatrix.sync.aligned.m8n8.x4.shared.b16 {%0,%1,%2,%3}, [%4];"
                 : "=r"(d[0]), "=r"(d[1]), "=r"(d[2]), "=r"(d[3]) : "r"(addr));
}
__device__ __forceinline__ void imma(int* c, const uint32_t* a, const uint32_t* b) {
    asm volatile(
        "mma.sync.aligned.m16n8k32.row.col.s32.s8.s8.s32 "
        "{%0,%1,%2,%3}, {%4,%5,%6,%7}, {%8,%9}, {%0,%1,%2,%3};"
        : "+r"(c[0]), "+r"(c[1]), "+r"(c[2]), "+r"(c[3])
        : "r"(a[0]), "r"(a[1]), "r"(a[2]), "r"(a[3]), "r"(b[0]), "r"(b[1]));
}
__device__ __forceinline__ void dp4a_acc(int& c, uint32_t a, uint32_t b) {
    asm volatile("dp4a.s32.s32 %0, %1, %2, %0;" : "+r"(c) : "r"(a), "r"(b));
}

// -------- preprocessing --------
__global__ void precomp_scales(const float* __restrict__ in_scale,
                               const float* __restrict__ act,
                               const float* __restrict__ w_scale) {
    int i = blockIdx.x * blockDim.x + threadIdx.x;
    float a = act[0];
    if (i < KDIM) g_comb[i] = __fdiv_rn(in_scale[i], a);
    if (i < NDIM) g_sc[i] = a * w_scale[i];
}

__global__ void quant_x(const float* __restrict__ x, int total4) {
    int i = blockIdx.x * blockDim.x + threadIdx.x;
    if (i >= total4) return;
    float4 v = reinterpret_cast<const float4*>(x)[i];
    int col = (i & (KDIM / 4 - 1)) * 4;
    int q0 = min(max(__float2int_rn(v.x * g_comb[col + 0]), -127), 127);
    int q1 = min(max(__float2int_rn(v.y * g_comb[col + 1]), -127), 127);
    int q2 = min(max(__float2int_rn(v.z * g_comb[col + 2]), -127), 127);
    int q3 = min(max(__float2int_rn(v.w * g_comb[col + 3]), -127), 127);
    uint32_t p = (uint32_t)(q0 & 0xFF) | ((uint32_t)(q1 & 0xFF) << 8) |
                 ((uint32_t)(q2 & 0xFF) << 16) | ((uint32_t)(q3 & 0xFF) << 24);
    reinterpret_cast<uint32_t*>(g_A8)[i] = p;
}

__global__ void conv_w(const int* __restrict__ w, int total4) {
    int i = blockIdx.x * blockDim.x + threadIdx.x;
    if (i >= total4) return;
    int4 v = reinterpret_cast<const int4*>(w)[i];
    uint32_t p = (uint32_t)(v.x & 0xFF) | ((uint32_t)(v.y & 0xFF) << 8) |
                 ((uint32_t)(v.z & 0xFF) << 16) | ((uint32_t)(v.w & 0xFF) << 24);
    reinterpret_cast<uint32_t*>(g_B8)[i] = p;
}

// -------- shared tile loader (A then B, XOR-swizzled, 256 threads) --------
__device__ __forceinline__ void load_stage(uint32_t sm, const char* gA, const char* gB,
                                           int kt, int t) {
    const char* ga = gA + (size_t)kt * BK;
    const char* gb = gB + (size_t)kt * BK;
#pragma unroll
    for (int i = 0; i < 4; i++) {
        int slot = t + i * 256;
        int row = slot >> 3, seg = slot & 7;
        cp16(sm + row * 128 + ((seg ^ (row & 7)) << 4),
             ga + (size_t)row * KDIM + seg * 16);
    }
#pragma unroll
    for (int i = 0; i < 4; i++) {
        int slot = t + i * 256;
        int row = slot >> 3, seg = slot & 7;
        cp16(sm + BM * 128 + row * 128 + ((seg ^ (row & 7)) << 4),
             gb + (size_t)row * KDIM + seg * 16);
    }
}

// -------- hybrid GEMM kernel: 512 threads, warps 0-7 IMMA, warps 8-15 dp4a --------
__global__ __launch_bounds__(512, 1)
void gemm_kernel(const float* __restrict__ bias, float* __restrict__ out) {
    extern __shared__ __align__(1024) char smem[];
    uint32_t sb = smem_u32(smem);
    int tid = threadIdx.x;
    int ntile = blockIdx.x, mtile = blockIdx.y;

    const char* gA = (const char*)g_A8 + (size_t)mtile * BM * KDIM;
    const char* gB = (const char*)g_B8 + (size_t)ntile * BN * KDIM;

    int c[2][8][4];    // IMMA accumulators (tid < 256)

    if (tid < 256) {
        // ================= IMMA group: k-tiles [0, KI) =================
        int lane = tid & 31, wid = tid >> 5;
        int warp_m = wid >> 1, warp_n = wid & 1;     // 4x2 warps, warp tile 32x64

        int t = lane >> 3, r = lane & 7;
        int rowA[2], rowB[4];
#pragma unroll
        for (int im = 0; im < 2; im++) rowA[im] = warp_m * 32 + im * 16 + (t & 1) * 8 + r;
        int segA = t >> 1;
#pragma unroll
        for (int nb = 0; nb < 4; nb++) rowB[nb] = warp_n * 64 + nb * 16 + (t >> 1) * 8 + r;
        int segB = t & 1;

#pragma unroll
        for (int im = 0; im < 2; im++)
#pragma unroll
            for (int n8 = 0; n8 < 8; n8++)
#pragma unroll
                for (int q = 0; q < 4; q++) c[im][n8][q] = 0;

        load_stage(sb + 0 * STAGE_BYTES, gA, gB, 0, tid);
        asm volatile("cp.async.commit_group;" ::: "memory");
        load_stage(sb + 1 * STAGE_BYTES, gA, gB, 1, tid);
        asm volatile("cp.async.commit_group;" ::: "memory");

#pragma unroll 1
        for (int kt = 0; kt < KI; kt++) {
            int s = kt % IMMA_STAGES;
            asm volatile("cp.async.wait_group 1;" ::: "memory");
            asm volatile("bar.sync 1, 256;" ::: "memory");

            if (kt + 2 < KI)
                load_stage(sb + ((kt + 2) % IMMA_STAGES) * STAGE_BYTES, gA, gB, kt + 2, tid);
            asm volatile("cp.async.commit_group;" ::: "memory");

            uint32_t sA = sb + s * STAGE_BYTES;
            uint32_t sB = sA + BM * 128;

#pragma unroll
            for (int j = 0; j < 4; j++) {
                uint32_t a[2][4];
#pragma unroll
                for (int im = 0; im < 2; im++) {
                    int seg = 2 * j + segA;
                    ldsm4(a[im], sA + rowA[im] * 128 + ((seg ^ (rowA[im] & 7)) << 4));
                }
                uint32_t bfr[8][2];
#pragma unroll
                for (int nb = 0; nb < 4; nb++) {
                    uint32_t r4[4];
                    int seg = 2 * j + segB;
                    ldsm4(r4, sB + rowB[nb] * 128 + ((seg ^ (rowB[nb] & 7)) << 4));
                    bfr[2 * nb][0] = r4[0]; bfr[2 * nb][1] = r4[1];
                    bfr[2 * nb + 1][0] = r4[2]; bfr[2 * nb + 1][1] = r4[3];
                }
#pragma unroll
                for (int im = 0; im < 2; im++)
#pragma unroll
                    for (int n8 = 0; n8 < 8; n8++)
                        imma(c[im][n8], a[im], bfr[n8]);
            }
        }
    } else {
        // ================= dp4a group: k-tiles [KI, KT), 3-stage pipeline =================
        int dt = tid - 256;
        int dl = dt & 31, dwid = dt >> 5;
        int wm = dwid >> 2, wn = dwid & 3;   // 2x4 warps, warp tile 64x32
        int tm = dl >> 2, tn = dl & 3;       // 8x4 threads, thread tile 8x8

        int cd[8][8];
#pragma unroll
        for (int i = 0; i < 8; i++)
#pragma unroll
            for (int j = 0; j < 8; j++) cd[i][j] = 0;

        uint32_t dbase = sb + DP_OFF;

        load_stage(dbase + 0 * STAGE_BYTES, gA, gB, KI + 0, dt);
        asm volatile("cp.async.commit_group;" ::: "memory");
        load_stage(dbase + 1 * STAGE_BYTES, gA, gB, KI + 1, dt);
        asm volatile("cp.async.commit_group;" ::: "memory");

#pragma unroll 1
        for (int kt = 0; kt < KD; kt++) {
            int s = kt % DP_STAGES;
            asm volatile("cp.async.wait_group 1;" ::: "memory");
            asm volatile("bar.sync 2, 256;" ::: "memory");

            if (kt + 2 < KD)
                load_stage(dbase + ((kt + 2) % DP_STAGES) * STAGE_BYTES, gA, gB, KI + kt + 2, dt);
            asm volatile("cp.async.commit_group;" ::: "memory");

            uint32_t sA = dbase + s * STAGE_BYTES;
            uint32_t sB = sA + BM * 128;

            // per-thread base addresses (low bits 4-6 hold the XOR-swizzle key)
            uint32_t aA = sA + (uint32_t)((wm * 64 + tm) * 128 + (tm << 4));
            uint32_t bE = sB + (uint32_t)((wn * 32 + tn) * 128 + (tn << 4));
            uint32_t bO = bE + 512 + 64;

#pragma unroll 1
            for (int seg = 0; seg < 8; seg++) {
                uint32_t as  = aA ^ (uint32_t)(seg << 4);
                uint32_t bsE = bE ^ (uint32_t)(seg << 4);
                uint32_t bsO = bO ^ (uint32_t)(seg << 4);
#pragma unroll
                for (int h = 0; h < 2; h++) {
                    uint32_t a[8][2], b[8][2];
#pragma unroll
                    for (int i = 0; i < 8; i++)
                        asm volatile("ld.shared.v2.b32 {%0,%1}, [%2];"
                                     : "=r"(a[i][0]), "=r"(a[i][1])
                                     : "r"(as + i * 1024 + h * 8));
#pragma unroll
                    for (int j = 0; j < 8; j++) {
                        uint32_t base = (j & 1) ? bsO : bsE;
                        asm volatile("ld.shared.v2.b32 {%0,%1}, [%2];"
                                     : "=r"(b[j][0]), "=r"(b[j][1])
                                     : "r"(base + (j >> 1) * 1024 + h * 8));
                    }
#pragma unroll
                    for (int i = 0; i < 8; i++)
#pragma unroll
                        for (int j = 0; j < 8; j++) {
                            dp4a_acc(cd[i][j], a[i][0], b[j][0]);
                            dp4a_acc(cd[i][j], a[i][1], b[j][1]);
                        }
                }
            }
        }

        // all dp4a warps done reading stage buffers before overwriting with partials
        asm volatile("bar.sync 2, 256;" ::: "memory");

        // write partial int32 sums to smem (conflict-free via stride 132)
        int* part = (int*)(smem + DP_OFF);
        int prow = wm * 64 + tm, pcol = wn * 32 + tn;
#pragma unroll
        for (int i = 0; i < 8; i++)
#pragma unroll
            for (int j = 0; j < 8; j++)
                part[(prow + 8 * i) * PART_STRIDE + pcol + 4 * j] = cd[i][j];
    }

    __syncthreads();   // dp4a partials visible; IMMA warps done

    if (tid < 256) {
        // ============ merged epilogue: add partials, dequant, store ============
        int lane = tid & 31, wid = tid >> 5;
        int warp_m = wid >> 1, warp_n = wid & 1;
        const int* part = (const int*)(smem + DP_OFF);

        int rl = warp_m * 32 + (lane >> 2);
        int cl = warp_n * 64 + (lane & 3) * 2;
        int m0 = mtile * BM + rl;
        int n0 = ntile * BN + cl;

#pragma unroll
        for (int im = 0; im < 2; im++) {
#pragma unroll
            for (int n8 = 0; n8 < 8; n8++) {
                int col = n0 + n8 * 8;
                int lc = cl + n8 * 8;
                float2 sc = *reinterpret_cast<const float2*>(&g_sc[col]);
                float2 bi = *reinterpret_cast<const float2*>(&bias[col]);
                int r0l = rl + im * 16, r1l = r0l + 8;
                int p00 = part[r0l * PART_STRIDE + lc];
                int p01 = part[r0l * PART_STRIDE + lc + 1];
                int p10 = part[r1l * PART_STRIDE + lc];
                int p11 = part[r1l * PART_STRIDE + lc + 1];
                int r0 = m0 + im * 16, r1 = r0 + 8;
                float2 v0, v1;
                v0.x = (float)(c[im][n8][0] + p00) * sc.x + bi.x;
                v0.y = (float)(c[im][n8][1] + p01) * sc.y + bi.y;
                v1.x = (float)(c[im][n8][2] + p10) * sc.x + bi.x;
                v1.y = (float)(c[im][n8][3] + p11) * sc.y + bi.y;
                *reinterpret_cast<float2*>(out + (size_t)r0 * NDIM + col) = v0;
                *reinterpret_cast<float2*>(out + (size_t)r1 * NDIM + col) = v1;
            }
        }
    }
}

// -------- launch --------
extern "C" void kernel_launch(void* const* d_in, const int* in_sizes, int n_in,
                              void* d_out, int out_size) {
    const float* x        = (const float*)d_in[0];
    const float* in_scale = (const float*)d_in[1];
    const float* act      = (const float*)d_in[2];
    const int*   w        = (const int*)d_in[3];
    const float* w_scale  = (const float*)d_in[4];
    const float* bias     = (const float*)d_in[5];
    float* out = (float*)d_out;

    int M = in_sizes[0] / KDIM;  // 8192

    cudaFuncSetAttribute(gemm_kernel, cudaFuncAttributeMaxDynamicSharedMemorySize, SMEM_TOTAL);

    precomp_scales<<<(KDIM + 255) / 256, 256>>>(in_scale, act, w_scale);

    int xa4 = (M * KDIM) / 4;
    quant_x<<<(xa4 + 255) / 256, 256>>>(x, xa4);

    int wb4 = (NDIM * KDIM) / 4;
    conv_w<<<(wb4 + 255) / 256, 256>>>(w, wb4);

    dim3 grid(NDIM / BN, M / BM);
    gemm_kernel<<<grid, 512, SMEM_TOTAL>>>(bias, out);
}

// round 6
// speedup vs baseline: 1.4708x; 1.0110x over previous
#include <cuda_runtime.h>
#include <cuda_bf16.h>
#include <cstdint>
#include <cstddef>

// Fixed problem dims: B=4, S=2048 -> M=8192, K=4096, N=4096
#define KDIM 4096
#define NDIM 4096
#define MMAX 8192

#define BM 128
#define BN 128
#define BK 128
#define KT (KDIM / BK)      // 32 k-tiles
#define KI 18               // k-tiles done by IMMA warps [0, KI)
#define KD (KT - KI)        // k-tiles done by dp4a warps [KI, KT)

#define STAGE_BYTES (BM * BK + BN * BK)       // 32768 (A 16K + B 16K)
#define IMMA_STAGES 3
#define DP_STAGES 4
#define DP_OFF (IMMA_STAGES * STAGE_BYTES)    // 98304
#define PART_STRIDE 132                        // padded int32 row stride
#define SMEM_TOTAL (DP_OFF + DP_STAGES * STAGE_BYTES)  // 229376

// -------- device scratch --------
__device__ int8_t g_A8[(size_t)MMAX * KDIM];
__device__ int8_t g_B8[(size_t)NDIM * KDIM];
__device__ float  g_comb[KDIM];
__device__ float  g_sc[NDIM];

// -------- helpers --------
__device__ __forceinline__ uint32_t smem_u32(const void* p) {
    uint32_t a;
    asm("{ .reg .u64 t; cvta.to.shared.u64 t, %1; cvt.u32.u64 %0, t; }" : "=r"(a) : "l"(p));
    return a;
}
__device__ __forceinline__ void cp16(uint32_t s, const void* g) {
    asm volatile("cp.async.cg.shared.global [%0], [%1], 16;" :: "r"(s), "l"(g));
}
__device__ __forceinline__ void ldsm4(uint32_t* d, uint32_t addr) {
    asm volatile("ldmatrix.sync.aligned.m8n8.x4.shared.b16 {%0,%1,%2,%3}, [%4];"
                 : "=r"(d[0]), "=r"(d[1]), "=r"(d[2]), "=r"(d[3]) : "r"(addr));
}
__device__ __forceinline__ void imma(int* c, const uint32_t* a, const uint32_t* b) {
    asm volatile(
        "mma.sync.aligned.m16n8k32.row.col.s32.s8.s8.s32 "
        "{%0,%1,%2,%3}, {%4,%5,%6,%7}, {%8,%9}, {%0,%1,%2,%3};"
        : "+r"(c[0]), "+r"(c[1]), "+r"(c[2]), "+r"(c[3])
        : "r"(a[0]), "r"(a[1]), "r"(a[2]), "r"(a[3]), "r"(b[0]), "r"(b[1]));
}
__device__ __forceinline__ void dp4a_acc(int& c, uint32_t a, uint32_t b) {
    asm volatile("dp4a.s32.s32 %0, %1, %2, %0;" : "+r"(c) : "r"(a), "r"(b));
}
__device__ __forceinline__ void lds128(uint32_t* d, uint32_t addr) {
    asm volatile("ld.shared.v4.b32 {%0,%1,%2,%3}, [%4];"
                 : "=r"(d[0]), "=r"(d[1]), "=r"(d[2]), "=r"(d[3]) : "r"(addr));
}

// -------- preprocessing --------
__global__ void precomp_scales(const float* __restrict__ in_scale,
                               const float* __restrict__ act,
                               const float* __restrict__ w_scale) {
    int i = blockIdx.x * blockDim.x + threadIdx.x;
    float a = act[0];
    if (i < KDIM) g_comb[i] = __fdiv_rn(in_scale[i], a);
    if (i < NDIM) g_sc[i] = a * w_scale[i];
}

__global__ void quant_x(const float* __restrict__ x, int total4) {
    int i = blockIdx.x * blockDim.x + threadIdx.x;
    if (i >= total4) return;
    float4 v = reinterpret_cast<const float4*>(x)[i];
    int col = (i & (KDIM / 4 - 1)) * 4;
    int q0 = min(max(__float2int_rn(v.x * g_comb[col + 0]), -127), 127);
    int q1 = min(max(__float2int_rn(v.y * g_comb[col + 1]), -127), 127);
    int q2 = min(max(__float2int_rn(v.z * g_comb[col + 2]), -127), 127);
    int q3 = min(max(__float2int_rn(v.w * g_comb[col + 3]), -127), 127);
    uint32_t p = (uint32_t)(q0 & 0xFF) | ((uint32_t)(q1 & 0xFF) << 8) |
                 ((uint32_t)(q2 & 0xFF) << 16) | ((uint32_t)(q3 & 0xFF) << 24);
    reinterpret_cast<uint32_t*>(g_A8)[i] = p;
}

__global__ void conv_w(const int* __restrict__ w, int total4) {
    int i = blockIdx.x * blockDim.x + threadIdx.x;
    if (i >= total4) return;
    int4 v = reinterpret_cast<const int4*>(w)[i];
    uint32_t p = (uint32_t)(v.x & 0xFF) | ((uint32_t)(v.y & 0xFF) << 8) |
                 ((uint32_t)(v.z & 0xFF) << 16) | ((uint32_t)(v.w & 0xFF) << 24);
    reinterpret_cast<uint32_t*>(g_B8)[i] = p;
}

// -------- shared tile loader (A then B, XOR-swizzled, 256 threads) --------
__device__ __forceinline__ void load_stage(uint32_t sm, const char* gA, const char* gB,
                                           int kt, int t) {
    const char* ga = gA + (size_t)kt * BK;
    const char* gb = gB + (size_t)kt * BK;
#pragma unroll
    for (int i = 0; i < 4; i++) {
        int slot = t + i * 256;
        int row = slot >> 3, seg = slot & 7;
        cp16(sm + row * 128 + ((seg ^ (row & 7)) << 4),
             ga + (size_t)row * KDIM + seg * 16);
    }
#pragma unroll
    for (int i = 0; i < 4; i++) {
        int slot = t + i * 256;
        int row = slot >> 3, seg = slot & 7;
        cp16(sm + BM * 128 + row * 128 + ((seg ^ (row & 7)) << 4),
             gb + (size_t)row * KDIM + seg * 16);
    }
}

// -------- hybrid GEMM kernel: 512 threads, warps 0-7 IMMA, warps 8-15 dp4a --------
__global__ __launch_bounds__(512, 1)
void gemm_kernel(const float* __restrict__ bias, float* __restrict__ out) {
    extern __shared__ __align__(1024) char smem[];
    uint32_t sb = smem_u32(smem);
    int tid = threadIdx.x;
    int ntile = blockIdx.x, mtile = blockIdx.y;

    const char* gA = (const char*)g_A8 + (size_t)mtile * BM * KDIM;
    const char* gB = (const char*)g_B8 + (size_t)ntile * BN * KDIM;

    int c[2][8][4];    // IMMA accumulators (tid < 256)

    if (tid < 256) {
        // ================= IMMA group: k-tiles [0, KI) =================
        int lane = tid & 31, wid = tid >> 5;
        int warp_m = wid >> 1, warp_n = wid & 1;     // 4x2 warps, warp tile 32x64

        int t = lane >> 3, r = lane & 7;
        int rowA[2], rowB[4];
#pragma unroll
        for (int im = 0; im < 2; im++) rowA[im] = warp_m * 32 + im * 16 + (t & 1) * 8 + r;
        int segA = t >> 1;
#pragma unroll
        for (int nb = 0; nb < 4; nb++) rowB[nb] = warp_n * 64 + nb * 16 + (t >> 1) * 8 + r;
        int segB = t & 1;

#pragma unroll
        for (int im = 0; im < 2; im++)
#pragma unroll
            for (int n8 = 0; n8 < 8; n8++)
#pragma unroll
                for (int q = 0; q < 4; q++) c[im][n8][q] = 0;

        load_stage(sb + 0 * STAGE_BYTES, gA, gB, 0, tid);
        asm volatile("cp.async.commit_group;" ::: "memory");
        load_stage(sb + 1 * STAGE_BYTES, gA, gB, 1, tid);
        asm volatile("cp.async.commit_group;" ::: "memory");

#pragma unroll 1
        for (int kt = 0; kt < KI; kt++) {
            int s = kt % IMMA_STAGES;
            asm volatile("cp.async.wait_group 1;" ::: "memory");
            asm volatile("bar.sync 1, 256;" ::: "memory");

            if (kt + 2 < KI)
                load_stage(sb + ((kt + 2) % IMMA_STAGES) * STAGE_BYTES, gA, gB, kt + 2, tid);
            asm volatile("cp.async.commit_group;" ::: "memory");

            uint32_t sA = sb + s * STAGE_BYTES;
            uint32_t sB = sA + BM * 128;

#pragma unroll
            for (int j = 0; j < 4; j++) {
                uint32_t a[2][4];
#pragma unroll
                for (int im = 0; im < 2; im++) {
                    int seg = 2 * j + segA;
                    ldsm4(a[im], sA + rowA[im] * 128 + ((seg ^ (rowA[im] & 7)) << 4));
                }
                uint32_t bfr[8][2];
#pragma unroll
                for (int nb = 0; nb < 4; nb++) {
                    uint32_t r4[4];
                    int seg = 2 * j + segB;
                    ldsm4(r4, sB + rowB[nb] * 128 + ((seg ^ (rowB[nb] & 7)) << 4));
                    bfr[2 * nb][0] = r4[0]; bfr[2 * nb][1] = r4[1];
                    bfr[2 * nb + 1][0] = r4[2]; bfr[2 * nb + 1][1] = r4[3];
                }
#pragma unroll
                for (int im = 0; im < 2; im++)
#pragma unroll
                    for (int n8 = 0; n8 < 8; n8++)
                        imma(c[im][n8], a[im], bfr[n8]);
            }
        }
    } else {
        // ======== dp4a group: k-tiles [KI, KT), 4-stage pipeline, v4 loads ========
        int dt = tid - 256;
        int dl = dt & 31, dwid = dt >> 5;
        int wm = dwid >> 2, wn = dwid & 3;   // 2x4 warps, warp tile 64x32
        int tm = dl >> 2, tn = dl & 3;       // 8x4 threads, thread tile 8x8

        int cd[8][8];
#pragma unroll
        for (int i = 0; i < 8; i++)
#pragma unroll
            for (int j = 0; j < 8; j++) cd[i][j] = 0;

        uint32_t dbase = sb + DP_OFF;

        load_stage(dbase + 0 * STAGE_BYTES, gA, gB, KI + 0, dt);
        asm volatile("cp.async.commit_group;" ::: "memory");
        load_stage(dbase + 1 * STAGE_BYTES, gA, gB, KI + 1, dt);
        asm volatile("cp.async.commit_group;" ::: "memory");
        load_stage(dbase + 2 * STAGE_BYTES, gA, gB, KI + 2, dt);
        asm volatile("cp.async.commit_group;" ::: "memory");

#pragma unroll 1
        for (int kt = 0; kt < KD; kt++) {
            int s = kt % DP_STAGES;
            asm volatile("cp.async.wait_group 2;" ::: "memory");
            asm volatile("bar.sync 2, 256;" ::: "memory");

            if (kt + 3 < KD)
                load_stage(dbase + ((kt + 3) % DP_STAGES) * STAGE_BYTES, gA, gB, KI + kt + 3, dt);
            asm volatile("cp.async.commit_group;" ::: "memory");

            uint32_t sA = dbase + s * STAGE_BYTES;
            uint32_t sB = sA + BM * 128;

            // per-thread base addresses (low bits 4-6 hold the XOR-swizzle key)
            uint32_t aA = sA + (uint32_t)((wm * 64 + tm) * 128 + (tm << 4));
            uint32_t bE = sB + (uint32_t)((wn * 32 + tn) * 128 + (tn << 4));
            uint32_t bO = bE + 512 + 64;

#pragma unroll 1
            for (int seg = 0; seg < 8; seg++) {
                uint32_t as  = aA ^ (uint32_t)(seg << 4);
                uint32_t bsE = bE ^ (uint32_t)(seg << 4);
                uint32_t bsO = bO ^ (uint32_t)(seg << 4);

                // load all 8 A vectors (16B each: covers both k-halves of this seg)
                uint32_t a[8][4];
#pragma unroll
                for (int i = 0; i < 8; i++)
                    lds128(a[i], as + i * 1024);

#pragma unroll
                for (int jh = 0; jh < 2; jh++) {
                    uint32_t b[4][4];
#pragma unroll
                    for (int jj = 0; jj < 4; jj++) {
                        int j = jh * 4 + jj;
                        uint32_t base = (j & 1) ? bsO : bsE;
                        lds128(b[jj], base + (j >> 1) * 1024);
                    }
#pragma unroll
                    for (int i = 0; i < 8; i++)
#pragma unroll
                        for (int jj = 0; jj < 4; jj++) {
                            int& acc = cd[i][jh * 4 + jj];
                            dp4a_acc(acc, a[i][0], b[jj][0]);
                            dp4a_acc(acc, a[i][1], b[jj][1]);
                            dp4a_acc(acc, a[i][2], b[jj][2]);
                            dp4a_acc(acc, a[i][3], b[jj][3]);
                        }
                }
            }
        }

        // all dp4a warps done reading stage buffers before overwriting with partials
        asm volatile("bar.sync 2, 256;" ::: "memory");

        // write partial int32 sums to smem (conflict-free via stride 132)
        int* part = (int*)(smem + DP_OFF);
        int prow = wm * 64 + tm, pcol = wn * 32 + tn;
#pragma unroll
        for (int i = 0; i < 8; i++)
#pragma unroll
            for (int j = 0; j < 8; j++)
                part[(prow + 8 * i) * PART_STRIDE + pcol + 4 * j] = cd[i][j];
    }

    __syncthreads();   // dp4a partials visible; IMMA warps done

    if (tid < 256) {
        // ============ merged epilogue: add partials, dequant, store ============
        int lane = tid & 31, wid = tid >> 5;
        int warp_m = wid >> 1, warp_n = wid & 1;
        const int* part = (const int*)(smem + DP_OFF);

        int rl = warp_m * 32 + (lane >> 2);
        int cl = warp_n * 64 + (lane & 3) * 2;
        int m0 = mtile * BM + rl;
        int n0 = ntile * BN + cl;

#pragma unroll
        for (int im = 0; im < 2; im++) {
#pragma unroll
            for (int n8 = 0; n8 < 8; n8++) {
                int col = n0 + n8 * 8;
                int lc = cl + n8 * 8;
                float2 sc = *reinterpret_cast<const float2*>(&g_sc[col]);
                float2 bi = *reinterpret_cast<const float2*>(&bias[col]);
                int r0l = rl + im * 16, r1l = r0l + 8;
                int p00 = part[r0l * PART_STRIDE + lc];
                int p01 = part[r0l * PART_STRIDE + lc + 1];
                int p10 = part[r1l * PART_STRIDE + lc];
                int p11 = part[r1l * PART_STRIDE + lc + 1];
                int r0 = m0 + im * 16, r1 = r0 + 8;
                float2 v0, v1;
                v0.x = (float)(c[im][n8][0] + p00) * sc.x + bi.x;
                v0.y = (float)(c[im][n8][1] + p01) * sc.y + bi.y;
                v1.x = (float)(c[im][n8][2] + p10) * sc.x + bi.x;
                v1.y = (float)(c[im][n8][3] + p11) * sc.y + bi.y;
                *reinterpret_cast<float2*>(out + (size_t)r0 * NDIM + col) = v0;
                *reinterpret_cast<float2*>(out + (size_t)r1 * NDIM + col) = v1;
            }
        }
    }
}

// -------- launch --------
extern "C" void kernel_launch(void* const* d_in, const int* in_sizes, int n_in,
                              void* d_out, int out_size) {
    const float* x        = (const float*)d_in[0];
    const float* in_scale = (const float*)d_in[1];
    const float* act      = (const float*)d_in[2];
    const int*   w        = (const int*)d_in[3];
    const float* w_scale  = (const float*)d_in[4];
    const float* bias     = (const float*)d_in[5];
    float* out = (float*)d_out;

    int M = in_sizes[0] / KDIM;  // 8192

    cudaFuncSetAttribute(gemm_kernel, cudaFuncAttributeMaxDynamicSharedMemorySize, SMEM_TOTAL);

    precomp_scales<<<(KDIM + 255) / 256, 256>>>(in_scale, act, w_scale);

    int xa4 = (M * KDIM) / 4;
    quant_x<<<(xa4 + 255) / 256, 256>>>(x, xa4);

    int wb4 = (NDIM * KDIM) / 4;
    conv_w<<<(wb4 + 255) / 256, 256>>>(w, wb4);

    dim3 grid(NDIM / BN, M / BM);
    gemm_kernel<<<grid, 512, SMEM_TOTAL>>>(bias, out);
}